// round 7
// baseline (speedup 1.0000x reference)
#include <cuda_runtime.h>
#include <math.h>

// Problem constants
#define S_LEN 16384
#define E_DIM 2048
#define H_DIM 1024
#define C_CLS 5
#define NCHUNK 256                        // colsum row chunks
#define ROWS_PER_CHUNK 64                 // S_LEN / NCHUNK
#define COLSUM_BLOCKS 512                 // NCHUNK * 2 column halves
#define HH_BLOCKS 1024                    // 2 layers * 4096 rows / 8 warps
#define N_REDUCERS 8

// Scratch (device allocation forbidden -> __device__ globals)
__device__ float g_part[NCHUNK * E_DIM];  // 2 MB partial column sums
__device__ float g_x[E_DIM];              // attn_applied == column sum
__device__ float g_hh0[4 * H_DIM];        // w_hh_l0 @ hidden[0]
__device__ float g_hh1[4 * H_DIM];        // w_hh_l1 @ hidden[1]
__device__ float g_h1[H_DIM];
__device__ float g_h2[H_DIM];
__device__ unsigned int g_cnt  = 0;       // colsum completion counter
__device__ unsigned int g_done = 0;       // reducer completion counter
__device__ unsigned int g_cnt2 = 0;       // ih1 completion counter

__device__ __forceinline__ float dot4(float4 a, float4 b) {
    return a.x * b.x + a.y * b.y + a.z * b.z + a.w * b.w;
}
__device__ __forceinline__ float sigf(float v) {
    return 1.0f / (1.0f + __expf(-v));
}
__device__ __forceinline__ float4 ldcs4(const float4* p) { return __ldcs(p); }

// ---------------------------------------------------------------------------
// Phase 1 (one launch): colsum partials + both hh GEMVs + (tail) colsum reduce.
//   blocks [0, 512):      colsum partials of encoder_hiddens (134 MB);
//                         the last 8 arrivals also reduce partials -> g_x
//   blocks [512, 1536):   hh GEMVs, warp-per-row (16.8 MB each layer)
// ---------------------------------------------------------------------------
__global__ void __launch_bounds__(256) fused_phase1(const float* __restrict__ enc,
                                                    const float* __restrict__ hidden,
                                                    const float* __restrict__ w_hh_l0,
                                                    const float* __restrict__ w_hh_l1) {
    const int bid = blockIdx.x;
    const int tid = threadIdx.x;
    __shared__ float4 xs[H_DIM / 4];          // hh activation stage (4 KB)
    __shared__ unsigned int s_arr;

    if (bid < COLSUM_BLOCKS) {
        // ---- column-sum partials: explicit 8-deep load batches (MLP=8) ----
        const int chunk = bid >> 1;
        const int c4 = (bid & 1) * 256 + tid;                 // float4 col [0,512)
        const float4* __restrict__ e4 = (const float4*)enc;
        const size_t base = (size_t)chunk * ROWS_PER_CHUNK * (E_DIM / 4) + c4;
        float4 acc = make_float4(0.f, 0.f, 0.f, 0.f);
#pragma unroll
        for (int b = 0; b < ROWS_PER_CHUNK / 8; b++) {
            float4 v[8];
#pragma unroll
            for (int u = 0; u < 8; u++)
                v[u] = ldcs4(&e4[base + (size_t)(b * 8 + u) * (E_DIM / 4)]);
#pragma unroll
            for (int u = 0; u < 8; u++) {
                acc.x += v[u].x; acc.y += v[u].y; acc.z += v[u].z; acc.w += v[u].w;
            }
        }
        ((float4*)g_part)[(size_t)chunk * (E_DIM / 4) + c4] = acc;

        // ---- completion counter; last 8 arrivals perform the reduce ----
        __threadfence();
        __syncthreads();
        if (tid == 0) s_arr = atomicAdd(&g_cnt, 1u);
        __syncthreads();
        const unsigned int a = s_arr;
        if (a >= COLSUM_BLOCKS - N_REDUCERS) {
            if (tid == 0) {
                while (atomicAdd(&g_cnt, 0u) < COLSUM_BLOCKS) { __nanosleep(64); }
            }
            __syncthreads();
            __threadfence();
            const int col = (int)(a - (COLSUM_BLOCKS - N_REDUCERS)) * 256 + tid; // [0,2048)
            float s = 0.f;
#pragma unroll 8
            for (int c = 0; c < NCHUNK; c++) s += g_part[c * E_DIM + col];
            g_x[col] = s;
            __threadfence();
            __syncthreads();
            if (tid == 0) {
                unsigned int d = atomicAdd(&g_done, 1u);
                if (d == N_REDUCERS - 1) {    // last reducer: reset for next replay
                    __threadfence();
                    g_cnt = 0; g_done = 0;
                }
            }
        }
    } else {
        // ---- hh GEMV: 8 warps, 1 gate-row each, x staged in shared ----
        const int b = bid - COLSUM_BLOCKS;
        const int sec = b >> 9;                               // 0: layer0, 1: layer1
        const int warp = tid >> 5, lane = tid & 31;
        const int row = (b & 511) * 8 + warp;                 // [0, 4096)
        const float* __restrict__ w = sec ? w_hh_l1 : w_hh_l0;
        const float4* __restrict__ hv4 = (const float4*)(hidden + sec * H_DIM);
        if (tid < H_DIM / 4) xs[tid] = hv4[tid];
        __syncthreads();
        const float4* __restrict__ w4 = (const float4*)(w + (size_t)row * H_DIM);
        float4 wv[8];
#pragma unroll
        for (int u = 0; u < 8; u++) wv[u] = ldcs4(&w4[u * 32 + lane]);
        float s = 0.f;
#pragma unroll
        for (int u = 0; u < 8; u++) s += dot4(wv[u], xs[u * 32 + lane]);
#pragma unroll
        for (int o = 16; o; o >>= 1) s += __shfl_down_sync(0xffffffffu, s, o);
        if (lane == 0) (sec ? g_hh1 : g_hh0)[row] = s;
    }
}

// ---------------------------------------------------------------------------
// ih GEMV + gate combine. Block = 256 thr = 8 warps handles 2 hidden units:
// warp w -> gate (w>>1), unit j0+(w&1). Activation staged in shared; weight
// loads batched 8-deep before any FMA (forced MLP=8). FC tail (layer 1):
// the last block to finish computes the 5-class head.
// ---------------------------------------------------------------------------
template <int IN, bool FC_TAIL>
__global__ void __launch_bounds__(256) lstm_ih_combine(const float* __restrict__ xin,
                                                       const float* __restrict__ cprev,
                                                       const float* __restrict__ w_ih,
                                                       const float* __restrict__ b_ih,
                                                       const float* __restrict__ b_hh,
                                                       const float* __restrict__ hhpart,
                                                       float* __restrict__ hout,
                                                       const float* __restrict__ fc_w,
                                                       const float* __restrict__ fc_b,
                                                       float* __restrict__ out) {
    __shared__ float4 xs[IN / 4];             // activation stage (<= 8 KB)
    __shared__ float sg[8];
    __shared__ unsigned int s_arr;
    const int tid = threadIdx.x;
    const int warp = tid >> 5, lane = tid & 31;
    const int j0 = blockIdx.x * 2;
    const int jl = warp & 1;                  // which of the 2 units
    const int gate = warp >> 1;
    const int row = gate * H_DIM + j0 + jl;

    // stage x
    const float4* __restrict__ x4 = (const float4*)xin;
#pragma unroll
    for (int t = tid; t < IN / 4; t += 256) xs[t] = x4[t];
    __syncthreads();

    const float4* __restrict__ w4 = (const float4*)(w_ih + (size_t)row * IN);
    float s = 0.f;
#pragma unroll
    for (int b = 0; b < IN / 1024; b++) {     // 2 batches (E) or 1 (H)
        float4 wv[8];
#pragma unroll
        for (int u = 0; u < 8; u++) wv[u] = ldcs4(&w4[b * 256 + u * 32 + lane]);
#pragma unroll
        for (int u = 0; u < 8; u++) s += dot4(wv[u], xs[b * 256 + u * 32 + lane]);
    }
#pragma unroll
    for (int o = 16; o; o >>= 1) s += __shfl_down_sync(0xffffffffu, s, o);
    if (lane == 0) sg[warp] = s;
    __syncthreads();
    if (tid < 2) {
        const int j = j0 + tid;
        float gi = sg[0 + tid] + hhpart[0 * H_DIM + j] + b_ih[0 * H_DIM + j] + b_hh[0 * H_DIM + j];
        float gf = sg[2 + tid] + hhpart[1 * H_DIM + j] + b_ih[1 * H_DIM + j] + b_hh[1 * H_DIM + j];
        float gg = sg[4 + tid] + hhpart[2 * H_DIM + j] + b_ih[2 * H_DIM + j] + b_hh[2 * H_DIM + j];
        float go = sg[6 + tid] + hhpart[3 * H_DIM + j] + b_ih[3 * H_DIM + j] + b_hh[3 * H_DIM + j];
        float c2 = sigf(gf) * cprev[j] + sigf(gi) * tanhf(gg);
        hout[j] = sigf(go) * tanhf(c2);
        __threadfence();
    }

    if (FC_TAIL) {
        __syncthreads();
        if (tid == 0) s_arr = atomicAdd(&g_cnt2, 1u);
        __syncthreads();
        if (s_arr == (H_DIM / 2) - 1) {       // last block: all h2 written
            __threadfence();
            if (warp < C_CLS) {
                const float4* __restrict__ fw4 = (const float4*)(fc_w + (size_t)warp * H_DIM);
                const float4* __restrict__ h4 = (const float4*)hout;
                float fs = 0.f;
#pragma unroll
                for (int u = 0; u < 8; u++) fs += dot4(fw4[u * 32 + lane], h4[u * 32 + lane]);
#pragma unroll
                for (int o = 16; o; o >>= 1) fs += __shfl_down_sync(0xffffffffu, fs, o);
                if (lane == 0) out[warp] = fs + fc_b[warp];
            }
            __syncthreads();
            if (tid == 0) g_cnt2 = 0;         // reset for next replay
        }
    }
}

extern "C" void kernel_launch(void* const* d_in, const int* in_sizes, int n_in,
                              void* d_out, int out_size) {
    const float* enc     = (const float*)d_in[0];   // (S, 1, E)
    const float* hidden  = (const float*)d_in[1];   // (2, 1, H)
    const float* c_in    = (const float*)d_in[2];   // (2, 1, H)
    // d_in[3] attn_w, d_in[4] attn_b: dead — softmax over the size-1 output
    // axis is identically 1, so attn_applied is a plain column sum of enc.
    const float* w_ih_l0 = (const float*)d_in[5];
    const float* w_hh_l0 = (const float*)d_in[6];
    const float* b_ih_l0 = (const float*)d_in[7];
    const float* b_hh_l0 = (const float*)d_in[8];
    const float* w_ih_l1 = (const float*)d_in[9];
    const float* w_hh_l1 = (const float*)d_in[10];
    const float* b_ih_l1 = (const float*)d_in[11];
    const float* b_hh_l1 = (const float*)d_in[12];
    const float* fc_w    = (const float*)d_in[13];
    const float* fc_b    = (const float*)d_in[14];
    float* out = (float*)d_out;

    float* x_dev;   cudaGetSymbolAddress((void**)&x_dev,   g_x);
    float* hh0_dev; cudaGetSymbolAddress((void**)&hh0_dev, g_hh0);
    float* hh1_dev; cudaGetSymbolAddress((void**)&hh1_dev, g_hh1);
    float* h1_dev;  cudaGetSymbolAddress((void**)&h1_dev,  g_h1);
    float* h2_dev;  cudaGetSymbolAddress((void**)&h2_dev,  g_h2);

    // 1) colsum partials + both hh GEMVs + in-grid reduce -> g_x
    fused_phase1<<<COLSUM_BLOCKS + HH_BLOCKS, 256>>>(enc, hidden, w_hh_l0, w_hh_l1);

    // 2) LSTM layer 0: ih GEMV (E=2048) + combine -> h1
    lstm_ih_combine<E_DIM, false><<<H_DIM / 2, 256>>>(x_dev, c_in, w_ih_l0, b_ih_l0,
                                                      b_hh_l0, hh0_dev, h1_dev,
                                                      nullptr, nullptr, nullptr);

    // 3) LSTM layer 1: ih GEMV (H=1024) + combine -> h2, last block runs FC head
    lstm_ih_combine<H_DIM, true><<<H_DIM / 2, 256>>>(h1_dev, c_in + H_DIM, w_ih_l1, b_ih_l1,
                                                     b_hh_l1, hh1_dev, h2_dev,
                                                     fc_w, fc_b, out);
}